// round 11
// baseline (speedup 1.0000x reference)
#include <cuda_runtime.h>
#include <cuda.h>
#include <cuda_fp16.h>
#include <math.h>

// CollectNeighbourAverageAndMax: out[v] = concat(mean_k x[idx[v,k]], max_k x[idx[v,k]])
// V=100000, K=32, F=64.
//
// R10: TMA tile::gather4 gather (bypasses L1tex, which is the measured ~2.2
// cyc/line wall for all LDG-based variants). fp16 mirror row = 128B; one
// gather4 fetches 4 neighbor rows L2->SMEM. 8 ops per output row -> 4KB smem
// buffer per warp; consumers reduce from smem (conflict-free column reads).
// Host builds the CUtensorMap via cudaGetDriverEntryPointByVersion (no -lcuda
// needed) and falls back to the R9 scalar-LDG kernel if anything fails.

#define VV 100000
#define KK 32
#define FF 64
#define ROW_H2 (FF / 2)   // 32 half2 per row

__device__ __align__(128) __half2 g_xh[(size_t)VV * ROW_H2];   // 12.8 MB fp16 mirror

// ---- prepass: fp32 -> fp16 conversion (streaming hints) -------------------
__global__ void convert_kernel(const float* __restrict__ x) {
    const int i = blockIdx.x * blockDim.x + threadIdx.x;  // one float4 -> two half2
    const int n4 = VV * FF / 4;
    if (i >= n4) return;
    const float4 v = __ldcg(reinterpret_cast<const float4*>(x) + i);
    __half2 h0 = __floats2half2_rn(v.x, v.y);
    __half2 h1 = __floats2half2_rn(v.z, v.w);
    unsigned u0 = *reinterpret_cast<unsigned*>(&h0);
    unsigned u1 = *reinterpret_cast<unsigned*>(&h1);
    __stcg(reinterpret_cast<uint2*>(g_xh) + i, make_uint2(u0, u1));
}

__device__ __forceinline__ __half2 u2h(unsigned u) {
    return *reinterpret_cast<__half2*>(&u);
}

__device__ __forceinline__ uint32_t smem_u32(const void* p) {
    uint32_t a;
    asm("{ .reg .u64 t; cvta.to.shared.u64 t, %1; cvt.u32.u64 %0, t; }"
        : "=r"(a) : "l"(p));
    return a;
}

__device__ __forceinline__ void tma_gather4(uint32_t dst, const CUtensorMap* tmap,
                                            int r0, int r1, int r2, int r3,
                                            uint32_t mbar) {
    asm volatile(
        "cp.async.bulk.tensor.2d.tile::gather4.shared::cta.global.mbarrier::complete_tx::bytes "
        "[%0], [%1, {%2, %3, %4, %5, %6}], [%7];"
        :: "r"(dst), "l"(tmap), "r"(0), "r"(r0), "r"(r1), "r"(r2), "r"(r3),
           "r"(mbar)
        : "memory");
}

// ---- TMA main kernel: 8 warps/block, one output row per warp --------------
__global__ __launch_bounds__(256)
void collect_tma_kernel(const __grid_constant__ CUtensorMap tmap,
                        const int* __restrict__ idxs,
                        float* __restrict__ out) {
    __shared__ __align__(1024) uint4 rowbuf[8][256];   // 8 x 4KB neighbor buffers
    __shared__ __align__(8) unsigned long long mbar[8];

    const int wid  = threadIdx.x >> 5;
    const int lane = threadIdx.x & 31;
    const int row  = blockIdx.x * 8 + wid;          // 12500*8 == 100000 exactly

    const uint32_t mb  = smem_u32(&mbar[wid]);
    const uint32_t buf = smem_u32(&rowbuf[wid][0]);

    // Uniform index loads: all lanes get all 32 indices (broadcast wavefronts).
    const int4* __restrict__ idxq =
        reinterpret_cast<const int4*>(idxs + (size_t)row * KK);
    const int4 q0 = __ldg(idxq + 0), q1 = __ldg(idxq + 1);
    const int4 q2 = __ldg(idxq + 2), q3 = __ldg(idxq + 3);
    const int4 q4 = __ldg(idxq + 4), q5 = __ldg(idxq + 5);
    const int4 q6 = __ldg(idxq + 6), q7 = __ldg(idxq + 7);

    if (lane == 0) {
        asm volatile("mbarrier.init.shared.b64 [%0], 1;" :: "r"(mb) : "memory");
        asm volatile("fence.proxy.async.shared::cta;" ::: "memory");
    }
    __syncwarp();

    if (lane == 0) {
        asm volatile("mbarrier.arrive.expect_tx.shared.b64 _, [%0], %1;"
                     :: "r"(mb), "r"(4096u) : "memory");
        tma_gather4(buf + 0 * 512, &tmap, q0.x, q0.y, q0.z, q0.w, mb);
        tma_gather4(buf + 1 * 512, &tmap, q1.x, q1.y, q1.z, q1.w, mb);
        tma_gather4(buf + 2 * 512, &tmap, q2.x, q2.y, q2.z, q2.w, mb);
        tma_gather4(buf + 3 * 512, &tmap, q3.x, q3.y, q3.z, q3.w, mb);
        tma_gather4(buf + 4 * 512, &tmap, q4.x, q4.y, q4.z, q4.w, mb);
        tma_gather4(buf + 5 * 512, &tmap, q5.x, q5.y, q5.z, q5.w, mb);
        tma_gather4(buf + 6 * 512, &tmap, q6.x, q6.y, q6.z, q6.w, mb);
        tma_gather4(buf + 7 * 512, &tmap, q7.x, q7.y, q7.z, q7.w, mb);
    }

    // Wait for all 4KB to land (phase 0; mbarrier is single-use per launch).
    {
        unsigned done;
        asm volatile(
            "{\n\t.reg .pred p;\n\t"
            "mbarrier.try_wait.parity.acquire.cta.shared::cta.b64 p, [%1], 0;\n\t"
            "selp.b32 %0, 1, 0, p;\n\t}"
            : "=r"(done) : "r"(mb) : "memory");
        if (!done) {
            asm volatile(
                "{\n\t.reg .pred P1;\n\t"
                "WL_%=:\n\t"
                "mbarrier.try_wait.parity.acquire.cta.shared::cta.b64 P1, [%0], 0, 0x989680;\n\t"
                "@P1 bra.uni WD_%=;\n\t"
                "bra.uni WL_%=;\n\t"
                "WD_%=:\n\t}"
                :: "r"(mb) : "memory");
        }
    }

    // Reduce: lane l owns features (2l, 2l+1) = 4B column at offset l*4 in
    // each 128B row. Conflict-free LDS.32, same tree as R9 (same rel_err).
    const unsigned* __restrict__ p =
        reinterpret_cast<const unsigned*>(&rowbuf[wid][0]) + lane;

    float2  sum = make_float2(0.f, 0.f);
    __half2 mx  = u2h(0xFBFFFBFFu);    // half2(-65504, -65504)

    #pragma unroll
    for (int c = 0; c < KK / 8; c++) {
        unsigned v[8];
        #pragma unroll
        for (int j = 0; j < 8; j++) v[j] = p[(8 * c + j) * 32];
        #pragma unroll
        for (int j = 0; j < 8; j++) mx = __hmax2(mx, u2h(v[j]));
        __half2 s01 = __hadd2(u2h(v[0]), u2h(v[1]));
        __half2 s23 = __hadd2(u2h(v[2]), u2h(v[3]));
        __half2 s45 = __hadd2(u2h(v[4]), u2h(v[5]));
        __half2 s67 = __hadd2(u2h(v[6]), u2h(v[7]));
        __half2 s   = __hadd2(__hadd2(s01, s23), __hadd2(s45, s67));
        const float2 sf = __half22float2(s);
        sum.x += sf.x;
        sum.y += sf.y;
    }

    float* o = out + (size_t)row * (2 * FF);
    reinterpret_cast<float2*>(o)[lane] =
        make_float2(sum.x * (1.0f / KK), sum.y * (1.0f / KK));      // mean half
    const float2 mf = __half22float2(mx);
    reinterpret_cast<float2*>(o + FF)[lane] = mf;                   // max half
}

// ---- fallback: R9 scalar-LDG gather (proven 33us main) --------------------
__global__ __launch_bounds__(256, 8)
void collect_nbr_kernel(const int* __restrict__ idxs,
                        float* __restrict__ out) {
    const int row  = (blockIdx.x * blockDim.x + threadIdx.x) >> 5;
    const int lane = threadIdx.x & 31;
    if (row >= VV) return;

    float2  sum = make_float2(0.f, 0.f);
    __half2 mx  = u2h(0xFBFFFBFFu);

    const unsigned* __restrict__ xb =
        reinterpret_cast<const unsigned*>(g_xh) + lane;
    const int4* __restrict__ idxq =
        reinterpret_cast<const int4*>(idxs + (size_t)row * KK);

    #pragma unroll
    for (int c = 0; c < KK / 8; c++) {
        const int4 qa = __ldg(idxq + 2 * c);
        const int4 qb = __ldg(idxq + 2 * c + 1);
        unsigned v0 = __ldg(xb + (size_t)qa.x * ROW_H2);
        unsigned v1 = __ldg(xb + (size_t)qa.y * ROW_H2);
        unsigned v2 = __ldg(xb + (size_t)qa.z * ROW_H2);
        unsigned v3 = __ldg(xb + (size_t)qa.w * ROW_H2);
        unsigned v4 = __ldg(xb + (size_t)qb.x * ROW_H2);
        unsigned v5 = __ldg(xb + (size_t)qb.y * ROW_H2);
        unsigned v6 = __ldg(xb + (size_t)qb.z * ROW_H2);
        unsigned v7 = __ldg(xb + (size_t)qb.w * ROW_H2);

        mx = __hmax2(mx, u2h(v0)); mx = __hmax2(mx, u2h(v1));
        mx = __hmax2(mx, u2h(v2)); mx = __hmax2(mx, u2h(v3));
        mx = __hmax2(mx, u2h(v4)); mx = __hmax2(mx, u2h(v5));
        mx = __hmax2(mx, u2h(v6)); mx = __hmax2(mx, u2h(v7));

        __half2 s01 = __hadd2(u2h(v0), u2h(v1));
        __half2 s23 = __hadd2(u2h(v2), u2h(v3));
        __half2 s45 = __hadd2(u2h(v4), u2h(v5));
        __half2 s67 = __hadd2(u2h(v6), u2h(v7));
        __half2 s   = __hadd2(__hadd2(s01, s23), __hadd2(s45, s67));
        const float2 sf = __half22float2(s);
        sum.x += sf.x;
        sum.y += sf.y;
    }

    float* o = out + (size_t)row * (2 * FF);
    reinterpret_cast<float2*>(o)[lane] =
        make_float2(sum.x * (1.0f / KK), sum.y * (1.0f / KK));
    const float2 mf = __half22float2(mx);
    reinterpret_cast<float2*>(o + FF)[lane] = mf;
}

// ---- host -----------------------------------------------------------------
typedef CUresult (*EncodeTiledFn)(
    CUtensorMap*, CUtensorMapDataType, cuuint32_t, void*,
    const cuuint64_t*, const cuuint64_t*, const cuuint32_t*, const cuuint32_t*,
    CUtensorMapInterleave, CUtensorMapSwizzle, CUtensorMapL2promotion,
    CUtensorMapFloatOOBfill);

extern "C" void kernel_launch(void* const* d_in, const int* in_sizes, int n_in,
                              void* d_out, int out_size) {
    const float* x    = (const float*)d_in[0];
    const int*   idxs = (const int*)d_in[1];
    float*       out  = (float*)d_out;

    const int n4 = VV * FF / 4;
    convert_kernel<<<(n4 + 255) / 256, 256>>>(x);

    // Build tensormap for g_xh (deterministic; done every call, no statics).
    bool tma_ok = false;
    CUtensorMap tmap;
    void* xh_ptr = nullptr;
    if (cudaGetSymbolAddress(&xh_ptr, g_xh) == cudaSuccess && xh_ptr) {
        EncodeTiledFn fn = nullptr;
        cudaDriverEntryPointQueryResult qr;
#if CUDART_VERSION >= 12050
        cudaError_t e = cudaGetDriverEntryPointByVersion(
            "cuTensorMapEncodeTiled", (void**)&fn, 12050,
            cudaEnableDefault, &qr);
#else
        cudaError_t e = cudaGetDriverEntryPoint(
            "cuTensorMapEncodeTiled", (void**)&fn, cudaEnableDefault, &qr);
#endif
        if (e == cudaSuccess && fn) {
            cuuint64_t dims[2]    = {FF, VV};          // {64 halves, 100000 rows}
            cuuint64_t strides[1] = {FF * 2};          // 128B row stride
            cuuint32_t box[2]     = {FF, 1};           // one 128B row per gather lane
            cuuint32_t es[2]      = {1, 1};
            CUresult r = fn(&tmap, CU_TENSOR_MAP_DATA_TYPE_FLOAT16, 2, xh_ptr,
                            dims, strides, box, es,
                            CU_TENSOR_MAP_INTERLEAVE_NONE,
                            CU_TENSOR_MAP_SWIZZLE_NONE,
                            CU_TENSOR_MAP_L2_PROMOTION_L2_128B,
                            CU_TENSOR_MAP_FLOAT_OOB_FILL_NONE);
            tma_ok = (r == CUDA_SUCCESS);
        }
    }

    if (tma_ok) {
        collect_tma_kernel<<<VV / 8, 256>>>(tmap, idxs, out);   // 12500 blocks
    } else {
        const int threads = 256;
        const int blocks = (VV + (threads / 32) - 1) / (threads / 32);
        collect_nbr_kernel<<<blocks, threads>>>(idxs, out);
    }
}

// round 12
// speedup vs baseline: 1.1005x; 1.1005x over previous
#include <cuda_runtime.h>
#include <cuda_fp16.h>
#include <math.h>

// CollectNeighbourAverageAndMax: out[v] = concat(mean_k x[idx[v,k]], max_k x[idx[v,k]])
// V=100000, K=32, F=64.
//
// R11: back to the proven scalar-LDG gather (R9: main 33us, L1-fill-port bound
// at 75% busy). The fill floor is ~25us (410MB / 148SM / 64B-per-cyc fill);
// the 25% busy gap is per-warp issue duty cycle: one row per warp = one
// dependency chain, loads stall behind the reduce. Fix: TWO independent row
// streams per warp (rows 2w, 2w+1), interleaved batch-4 gathers, so one row's
// loads issue while the other's reduce drains. Occupancy held at ~87%
// (launch_bounds(256,7), ~35 regs).
//  - fp16 mirror (12.8MB static): one row = 128B = one L1 line.
//  - gathers: warp-wide LDG.32, one line per instruction (established optimum).
//  - idx: uniform int4 loads (broadcast wavefronts, no SHFL).
//  - max in half2 (exact); sum tree-of-4 fp16 then fp32 promote per chunk.

#define VV 100000
#define KK 32
#define FF 64
#define ROW_H2 (FF / 2)   // 32 half2 per row

__device__ __align__(128) __half2 g_xh[(size_t)VV * ROW_H2];   // 12.8 MB mirror

// ---- prepass: fp32 -> fp16, 32B in / 16B out per thread -------------------
__global__ void convert_kernel(const float* __restrict__ x) {
    const int i = blockIdx.x * blockDim.x + threadIdx.x;   // one uint4 out
    const int n = VV * FF / 8;
    if (i >= n) return;
    const float4 a = __ldcg(reinterpret_cast<const float4*>(x) + 2 * i);
    const float4 b = __ldcg(reinterpret_cast<const float4*>(x) + 2 * i + 1);
    __half2 h0 = __floats2half2_rn(a.x, a.y);
    __half2 h1 = __floats2half2_rn(a.z, a.w);
    __half2 h2 = __floats2half2_rn(b.x, b.y);
    __half2 h3 = __floats2half2_rn(b.z, b.w);
    uint4 r;
    r.x = *reinterpret_cast<unsigned*>(&h0);
    r.y = *reinterpret_cast<unsigned*>(&h1);
    r.z = *reinterpret_cast<unsigned*>(&h2);
    r.w = *reinterpret_cast<unsigned*>(&h3);
    __stcg(reinterpret_cast<uint4*>(g_xh) + i, r);
}

__device__ __forceinline__ __half2 u2h(unsigned u) {
    return *reinterpret_cast<__half2*>(&u);
}

// ---- main gather/reduce: 2 independent rows per warp ----------------------
__global__ __launch_bounds__(256, 7)
void collect_nbr_kernel(const int* __restrict__ idxs,
                        float* __restrict__ out) {
    const int pair = (blockIdx.x * blockDim.x + threadIdx.x) >> 5;  // row pair id
    const int lane = threadIdx.x & 31;
    const int rowA = 2 * pair;
    const int rowB = 2 * pair + 1;
    if (rowA >= VV) return;

    float2  sumA = make_float2(0.f, 0.f), sumB = make_float2(0.f, 0.f);
    __half2 mxA  = u2h(0xFBFFFBFFu),     mxB  = u2h(0xFBFFFBFFu);

    const unsigned* __restrict__ xb =
        reinterpret_cast<const unsigned*>(g_xh) + lane;   // lane's slot in any row
    const int4* __restrict__ idxA =
        reinterpret_cast<const int4*>(idxs + (size_t)rowA * KK);
    const int4* __restrict__ idxB =
        reinterpret_cast<const int4*>(idxs + (size_t)rowB * KK);

    #pragma unroll
    for (int c = 0; c < KK / 4; c++) {
        // Uniform index loads (broadcast wavefront each, no SHFL).
        const int4 qa = __ldg(idxA + c);
        const int4 qb = __ldg(idxB + c);
        // 8 gathers in flight: 4 for row A, 4 for row B (independent chains).
        unsigned a0 = __ldg(xb + (size_t)qa.x * ROW_H2);
        unsigned a1 = __ldg(xb + (size_t)qa.y * ROW_H2);
        unsigned a2 = __ldg(xb + (size_t)qa.z * ROW_H2);
        unsigned a3 = __ldg(xb + (size_t)qa.w * ROW_H2);
        unsigned b0 = __ldg(xb + (size_t)qb.x * ROW_H2);
        unsigned b1 = __ldg(xb + (size_t)qb.y * ROW_H2);
        unsigned b2 = __ldg(xb + (size_t)qb.z * ROW_H2);
        unsigned b3 = __ldg(xb + (size_t)qb.w * ROW_H2);

        mxA = __hmax2(mxA, u2h(a0)); mxA = __hmax2(mxA, u2h(a1));
        mxA = __hmax2(mxA, u2h(a2)); mxA = __hmax2(mxA, u2h(a3));
        __half2 sa = __hadd2(__hadd2(u2h(a0), u2h(a1)),
                             __hadd2(u2h(a2), u2h(a3)));
        const float2 fa = __half22float2(sa);
        sumA.x += fa.x; sumA.y += fa.y;

        mxB = __hmax2(mxB, u2h(b0)); mxB = __hmax2(mxB, u2h(b1));
        mxB = __hmax2(mxB, u2h(b2)); mxB = __hmax2(mxB, u2h(b3));
        __half2 sb = __hadd2(__hadd2(u2h(b0), u2h(b1)),
                             __hadd2(u2h(b2), u2h(b3)));
        const float2 fb = __half22float2(sb);
        sumB.x += fb.x; sumB.y += fb.y;
    }

    const float inv = 1.0f / KK;
    float* oA = out + (size_t)rowA * (2 * FF);
    reinterpret_cast<float2*>(oA)[lane] = make_float2(sumA.x * inv, sumA.y * inv);
    reinterpret_cast<float2*>(oA + FF)[lane] = __half22float2(mxA);

    float* oB = out + (size_t)rowB * (2 * FF);
    reinterpret_cast<float2*>(oB)[lane] = make_float2(sumB.x * inv, sumB.y * inv);
    reinterpret_cast<float2*>(oB + FF)[lane] = __half22float2(mxB);
}

extern "C" void kernel_launch(void* const* d_in, const int* in_sizes, int n_in,
                              void* d_out, int out_size) {
    const float* x    = (const float*)d_in[0];
    const int*   idxs = (const int*)d_in[1];
    float*       out  = (float*)d_out;

    const int n = VV * FF / 8;                       // 800K threads
    convert_kernel<<<(n + 255) / 256, 256>>>(x);

    // One warp per row-pair: 50000 warps -> 6250 blocks of 256 threads.
    const int pairs = VV / 2;
    const int warps_per_block = 256 / 32;
    const int blocks = (pairs + warps_per_block - 1) / warps_per_block;
    collect_nbr_kernel<<<blocks, 256>>>(idxs, out);
}